// round 6
// baseline (speedup 1.0000x reference)
#include <cuda_runtime.h>
#include <math.h>

typedef unsigned long long ull;
typedef unsigned int u32;

#define B_  2
#define L_  2048
#define S_  2048
#define D_  256
#define H_  8
#define SPLITS 2
#define SHALF (S_ / SPLITS)      // 1024
#define LT 16                    // l-rows per block
#define ST 16
#define NT (SHALF / ST)          // 64

// ---------------- f32x2 packed math ----------------
#define PACK2(d, x, y) asm("mov.b64 %0, {%1, %2};" : "=l"(d) : "r"(__float_as_uint(x)), "r"(__float_as_uint(y)))
#define UNPACK2(x, y, d) do { u32 _lo, _hi; \
    asm("mov.b64 {%0, %1}, %2;" : "=r"(_lo), "=r"(_hi) : "l"(d)); \
    (x) = __uint_as_float(_lo); (y) = __uint_as_float(_hi); } while (0)
#define FMA2(d, a, b, c) asm("fma.rn.f32x2 %0, %1, %2, %3;" : "=l"(d) : "l"(a), "l"(b), "l"(c))
#define MUL2(d, a, b)    asm("mul.rn.f32x2 %0, %1, %2;"     : "=l"(d) : "l"(a), "l"(b))
#define ADD2(d, a, b)    asm("add.rn.f32x2 %0, %1, %2;"     : "=l"(d) : "l"(a), "l"(b))

__device__ __forceinline__ float ex2f(float x) {
    float r;
    asm("ex2.approx.ftz.f32 %0, %1;" : "=f"(r) : "f"(x));
    return r;
}

// ---------------- scratch ----------------
__device__ float g_Q[(size_t)B_ * L_ * D_];
__device__ float g_K[(size_t)B_ * S_ * D_];
__device__ float g_V[(size_t)B_ * S_ * D_];
__device__ float g_OP[(size_t)SPLITS * B_ * L_ * D_];
__device__ float g_SS[(size_t)SPLITS * B_ * H_ * L_];
__device__ float g_O[(size_t)B_ * L_ * D_];
__device__ float g_M[(size_t)B_ * L_ * D_];
__device__ float g_HB[(size_t)B_ * L_ * 2 * D_];
__device__ float g_T[(size_t)B_ * L_ * D_];

// ---------------- GEMM: Y[M,N] = X[M,K] @ W[N,K]^T ----------------
// Tile 64x64, 128 threads, microtile 4(m)x8(n), f32x2 pairs along n.
// A stored DUPLICATED in smem so a-operands load as packed ull pairs (no PACK
// in the inner loop).
template <bool RELU, bool SPLIT>
__global__ void __launch_bounds__(128) gemm64(
    const float* __restrict__ X, const float* __restrict__ X2,
    const float* __restrict__ W, float* __restrict__ Y,
    int M, int N, int K) {
    __shared__ float XsD[16][140];  // [k][2*m duplicated], 16B-aligned rows
    __shared__ float BsT[16][72];   // [k][n]
    const int bm = blockIdx.y * 64, bn = blockIdx.x * 64;
    const int t = threadIdx.x, tx = t & 7, ty = t >> 3;
    const int NTk = K >> 4;

    float4 xr[2], wr[2];
    #pragma unroll
    for (int i = 0; i < 2; i++) {   // prologue load k-tile 0
        int idx = t + 128 * i; int r = idx >> 2; int c = (idx & 3) * 4;
        if (SPLIT) xr[i] = (c < 256) ? *(const float4*)(X + (size_t)(bm + r) * 256 + c)
                                     : *(const float4*)(X2 + (size_t)(bm + r) * 256 + (c - 256));
        else       xr[i] = *(const float4*)(X + (size_t)(bm + r) * K + c);
        wr[i] = *(const float4*)(W + (size_t)(bn + r) * K + c);
    }

    ull acc[4][4]; ull zero; PACK2(zero, 0.0f, 0.0f);
    #pragma unroll
    for (int m = 0; m < 4; m++)
        #pragma unroll
        for (int n = 0; n < 4; n++) acc[m][n] = zero;

    for (int kt = 0; kt < NTk; kt++) {
        __syncthreads();
        #pragma unroll
        for (int i = 0; i < 2; i++) {
            int idx = t + 128 * i; int r = idx >> 2; int c = (idx & 3) * 4;
            ull d;
            PACK2(d, xr[i].x, xr[i].x); *(ull*)&XsD[c + 0][2 * r] = d;
            PACK2(d, xr[i].y, xr[i].y); *(ull*)&XsD[c + 1][2 * r] = d;
            PACK2(d, xr[i].z, xr[i].z); *(ull*)&XsD[c + 2][2 * r] = d;
            PACK2(d, xr[i].w, xr[i].w); *(ull*)&XsD[c + 3][2 * r] = d;
            BsT[c + 0][r] = wr[i].x; BsT[c + 1][r] = wr[i].y;
            BsT[c + 2][r] = wr[i].z; BsT[c + 3][r] = wr[i].w;
        }
        if (kt + 1 < NTk) {
            int k0 = (kt + 1) * 16;
            #pragma unroll
            for (int i = 0; i < 2; i++) {
                int idx = t + 128 * i; int r = idx >> 2; int c = (idx & 3) * 4;
                int kc = k0 + c;
                if (SPLIT) xr[i] = (kc < 256) ? *(const float4*)(X + (size_t)(bm + r) * 256 + kc)
                                              : *(const float4*)(X2 + (size_t)(bm + r) * 256 + (kc - 256));
                else       xr[i] = *(const float4*)(X + (size_t)(bm + r) * K + kc);
                wr[i] = *(const float4*)(W + (size_t)(bn + r) * K + kc);
            }
        }
        __syncthreads();
        #pragma unroll
        for (int kk = 0; kk < 16; kk++) {
            ulonglong2 a01 = *(const ulonglong2*)&XsD[kk][ty * 8];      // (a0,a0),(a1,a1)
            ulonglong2 a23 = *(const ulonglong2*)&XsD[kk][ty * 8 + 4];  // (a2,a2),(a3,a3)
            ulonglong2 b01 = *(const ulonglong2*)&BsT[kk][tx * 8];
            ulonglong2 b23 = *(const ulonglong2*)&BsT[kk][tx * 8 + 4];
            FMA2(acc[0][0], a01.x, b01.x, acc[0][0]); FMA2(acc[0][1], a01.x, b01.y, acc[0][1]);
            FMA2(acc[0][2], a01.x, b23.x, acc[0][2]); FMA2(acc[0][3], a01.x, b23.y, acc[0][3]);
            FMA2(acc[1][0], a01.y, b01.x, acc[1][0]); FMA2(acc[1][1], a01.y, b01.y, acc[1][1]);
            FMA2(acc[1][2], a01.y, b23.x, acc[1][2]); FMA2(acc[1][3], a01.y, b23.y, acc[1][3]);
            FMA2(acc[2][0], a23.x, b01.x, acc[2][0]); FMA2(acc[2][1], a23.x, b01.y, acc[2][1]);
            FMA2(acc[2][2], a23.x, b23.x, acc[2][2]); FMA2(acc[2][3], a23.x, b23.y, acc[2][3]);
            FMA2(acc[3][0], a23.y, b01.x, acc[3][0]); FMA2(acc[3][1], a23.y, b01.y, acc[3][1]);
            FMA2(acc[3][2], a23.y, b23.x, acc[3][2]); FMA2(acc[3][3], a23.y, b23.y, acc[3][3]);
        }
    }

    float o[4][8];
    #pragma unroll
    for (int m = 0; m < 4; m++)
        #pragma unroll
        for (int np = 0; np < 4; np++)
            UNPACK2(o[m][2 * np], o[m][2 * np + 1], acc[m][np]);
    #pragma unroll
    for (int r = 0; r < 4; r++) {
        if (RELU)
            #pragma unroll
            for (int n = 0; n < 8; n++) o[r][n] = fmaxf(o[r][n], 0.0f);
        float4 w0, w1;
        w0.x = o[r][0]; w0.y = o[r][1]; w0.z = o[r][2]; w0.w = o[r][3];
        w1.x = o[r][4]; w1.y = o[r][5]; w1.z = o[r][6]; w1.w = o[r][7];
        float* yp = Y + (size_t)(bm + ty * 4 + r) * N + bn + tx * 8;
        *(float4*)yp = w0;
        *(float4*)(yp + 4) = w1;
    }
}

// ---------------- fused attention, dim-split (2 threads per row) ----------------
// Block: 256 threads = 8 warps (warp = head). lane&15 = l-row (16 rows/block),
// lane>>4 = dim-half (16 dims each). Score halves combined via shfl_xor(16).
// Grid: (L/16, SPLITS, B) = 512 blocks, 3 blocks/SM.
// smem: Ks[2][16][256] | Vs[2][16][256] | Afs[2][16][17] = 67712 bytes.
#define ATTN_SMEM 67712

#define ISSUE_KV(t_, buf_) do { \
    const float* ksrc_ = Kb + (size_t)(sbase + (t_) * ST) * D_; \
    const float* vsrc_ = Vb + (size_t)(sbase + (t_) * ST) * D_; \
    u32 kd_ = kbase + (u32)(buf_) * 16384; \
    u32 vd_ = vbase + (u32)(buf_) * 16384; \
    _Pragma("unroll") \
    for (int i_ = 0; i_ < 4; i_++) { \
        int idx_ = tid + 256 * i_; int s_ = idx_ >> 6; int c_ = (idx_ & 63) * 4; \
        asm volatile("cp.async.cg.shared.global [%0], [%1], 16;" :: \
            "r"(kd_ + (u32)(s_ * 256 + c_) * 4), "l"(ksrc_ + s_ * 256 + c_)); \
        asm volatile("cp.async.cg.shared.global [%0], [%1], 16;" :: \
            "r"(vd_ + (u32)(s_ * 256 + c_) * 4), "l"(vsrc_ + s_ * 256 + c_)); \
    } \
    asm volatile("cp.async.commit_group;"); \
} while (0)

#define LOAD_AF(t_) do { \
    afr = afb[(size_t)(tid >> 4) * S_ + (t_) * ST + (tid & 15)]; \
} while (0)

#define STORE_AF(buf_) do { \
    Afs[(buf_) * 272 + (tid >> 4) * 17 + (tid & 15)] = afr; \
} while (0)

__global__ void __launch_bounds__(256, 3) attn3(
    const float* __restrict__ Qg, const float* __restrict__ Kg,
    const float* __restrict__ Vg, const float* __restrict__ af,
    float* __restrict__ Op, float* __restrict__ SSp) {
    extern __shared__ float sm[];
    float* Ksm = sm;                 // 2*16*256 = 8192 floats
    float* Vsm = sm + 8192;          // 8192
    float* Afs = sm + 16384;         // 2*16*17 = 544

    const int b = blockIdx.z, sp = blockIdx.y;
    const int l0 = blockIdx.x * LT;
    const int tid = threadIdx.x;
    const int w = tid >> 5, lane = tid & 31;
    const int lr = lane & 15, half = lane >> 4;
    const int dimoff = w * 32 + half * 16;
    const int sbase = sp * SHALF;
    const float* Kb  = Kg + (size_t)b * S_ * D_;
    const float* Vb  = Vg + (size_t)b * S_ * D_;
    const float* afb = af + ((size_t)b * L_ + l0) * S_ + sbase;
    const u32 smb = (u32)__cvta_generic_to_shared(sm);
    const u32 kbase = smb;
    const u32 vbase = smb + 8192 * 4;

    // q regs: this thread's 16 dims, pre-scaled by log2(e)/sqrt(32)
    ull q[8];
    {
        const float QS = 0.25503486f;  // 1.4426950408889634 / sqrt(32)
        const float* qr = Qg + ((size_t)b * L_ + l0 + lr) * D_ + dimoff;
        #pragma unroll
        for (int i = 0; i < 4; i++) {
            float4 f = *(const float4*)(qr + i * 4);
            f.x *= QS; f.y *= QS; f.z *= QS; f.w *= QS;
            PACK2(q[2 * i], f.x, f.y);
            PACK2(q[2 * i + 1], f.z, f.w);
        }
    }
    ull zero; PACK2(zero, 0.0f, 0.0f);
    ull o[8];
    #pragma unroll
    for (int i = 0; i < 8; i++) o[i] = zero;
    float ssum = 0.0f;
    float afr;

    // prologue
    ISSUE_KV(0, 0);
    LOAD_AF(0);
    ISSUE_KV(1, 1);
    STORE_AF(0);
    LOAD_AF(1);

    for (int t = 0; t < NT; t++) {
        const int buf = t & 1;
        if (t + 1 < NT) asm volatile("cp.async.wait_group 1;");
        else            asm volatile("cp.async.wait_group 0;");
        __syncthreads();
        if (t + 1 < NT) STORE_AF(buf ^ 1);
        if (t + 2 < NT) LOAD_AF(t + 2);

        const float* ks  = Ksm + buf * 4096 + dimoff;
        const float* vs  = Vsm + buf * 4096 + dimoff;
        const float* afl = Afs + buf * 272 + lr * 17;

        #pragma unroll 4
        for (int s = 0; s < ST; s++) {
            const ulonglong2* kp = (const ulonglong2*)(ks + s * 256);
            ull a0, a1;
            {
                ulonglong2 kv = kp[0];
                MUL2(a0, q[0], kv.x); MUL2(a1, q[1], kv.y);
            }
            { ulonglong2 kv = kp[1]; FMA2(a0, q[2], kv.x, a0); FMA2(a1, q[3], kv.y, a1); }
            { ulonglong2 kv = kp[2]; FMA2(a0, q[4], kv.x, a0); FMA2(a1, q[5], kv.y, a1); }
            { ulonglong2 kv = kp[3]; FMA2(a0, q[6], kv.x, a0); FMA2(a1, q[7], kv.y, a1); }
            ADD2(a0, a0, a1);
            float x0, x1; UNPACK2(x0, x1, a0);
            float x = x0 + x1;
            x += __shfl_xor_sync(0xffffffffu, x, 16);   // combine dim halves
            float p = ex2f(x * afl[s]);
            ssum += p;
            ull pp; PACK2(pp, p, p);
            const ulonglong2* vp = (const ulonglong2*)(vs + s * 256);
            #pragma unroll
            for (int j = 0; j < 4; j++) {
                ulonglong2 vv = vp[j];
                FMA2(o[2 * j],     pp, vv.x, o[2 * j]);
                FMA2(o[2 * j + 1], pp, vv.y, o[2 * j + 1]);
            }
        }
        __syncthreads();
        if (t + 2 < NT) ISSUE_KV(t + 2, buf);
    }

    // write raw partials (division happens in combine)
    float* op = Op + (((size_t)sp * B_ + b) * L_ + l0 + lr) * D_ + dimoff;
    #pragma unroll
    for (int j = 0; j < 4; j++) {
        float v0, v1, v2, v3;
        UNPACK2(v0, v1, o[2 * j]);
        UNPACK2(v2, v3, o[2 * j + 1]);
        float4 f; f.x = v0; f.y = v1; f.z = v2; f.w = v3;
        *(float4*)(op + j * 4) = f;
    }
    if (half == 0)
        SSp[(((size_t)sp * B_ + b) * H_ + w) * L_ + l0 + lr] = ssum;
}

// ---------------- combine split partials: O = (O0+O1)/(s0+s1) ----------------
__global__ void combine_kernel(const float* __restrict__ Op, const float* __restrict__ SSp,
                               float* __restrict__ O) {
    size_t i = (size_t)blockIdx.x * 256 + threadIdx.x;   // per float4
    size_t e = i * 4;
    int d = (int)(e & 255);
    size_t bl = e >> 8;                 // b*L + l
    int h = d >> 5;
    size_t b = bl >> 11, l = bl & 2047;
    float4 a = *(const float4*)(Op + e);
    float4 c = *(const float4*)(Op + (size_t)B_ * L_ * D_ + e);
    float s = SSp[(b * H_ + h) * L_ + l] + SSp[((size_t)B_ * H_ + b * H_ + h) * L_ + l];
    float inv = 1.0f / s;
    float4 r;
    r.x = (a.x + c.x) * inv; r.y = (a.y + c.y) * inv;
    r.z = (a.z + c.z) * inv; r.w = (a.w + c.w) * inv;
    *(float4*)(O + e) = r;
}

// ---------------- LayerNorm over D=256 ----------------
template <bool RESID>
__global__ void ln_kernel(const float* __restrict__ in, const float* __restrict__ g,
                          const float* __restrict__ bt, const float* __restrict__ resid,
                          float* __restrict__ out) {
    const size_t row = blockIdx.x;
    const int tid = threadIdx.x;
    float x = in[row * D_ + tid];
    __shared__ float red[256];
    red[tid] = x; __syncthreads();
    #pragma unroll
    for (int off = 128; off > 0; off >>= 1) {
        if (tid < off) red[tid] += red[tid + off];
        __syncthreads();
    }
    const float mean = red[0] * (1.0f / D_);
    __syncthreads();
    const float d = x - mean;
    red[tid] = d * d; __syncthreads();
    #pragma unroll
    for (int off = 128; off > 0; off >>= 1) {
        if (tid < off) red[tid] += red[tid + off];
        __syncthreads();
    }
    const float var = red[0] * (1.0f / D_);
    float y = d * rsqrtf(var + 1e-5f) * g[tid] + bt[tid];
    if (RESID) y += resid[row * D_ + tid];
    out[row * D_ + tid] = y;
}

// ---------------- launch ----------------
extern "C" void kernel_launch(void* const* d_in, const int* in_sizes, int n_in,
                              void* d_out, int out_size) {
    const float* x   = (const float*)d_in[0];
    const float* src = (const float*)d_in[1];
    const float* af  = (const float*)d_in[2];
    const float* Wq  = (const float*)d_in[3];
    const float* Wk  = (const float*)d_in[4];
    const float* Wv  = (const float*)d_in[5];
    const float* Wm  = (const float*)d_in[6];
    const float* W1  = (const float*)d_in[7];
    const float* W2  = (const float*)d_in[8];
    const float* g1  = (const float*)d_in[9];
    const float* b1  = (const float*)d_in[10];
    const float* g2  = (const float*)d_in[11];
    const float* b2  = (const float*)d_in[12];
    float* out = (float*)d_out;

    float *Q, *K, *V, *OP, *SS, *O, *M, *HB, *T;
    cudaGetSymbolAddress((void**)&Q,  g_Q);
    cudaGetSymbolAddress((void**)&K,  g_K);
    cudaGetSymbolAddress((void**)&V,  g_V);
    cudaGetSymbolAddress((void**)&OP, g_OP);
    cudaGetSymbolAddress((void**)&SS, g_SS);
    cudaGetSymbolAddress((void**)&O,  g_O);
    cudaGetSymbolAddress((void**)&M,  g_M);
    cudaGetSymbolAddress((void**)&HB, g_HB);
    cudaGetSymbolAddress((void**)&T,  g_T);

    cudaFuncSetAttribute(attn3, cudaFuncAttributeMaxDynamicSharedMemorySize, ATTN_SMEM);

    const int ML = B_ * L_;  // 4096

    // projections
    gemm64<false, false><<<dim3(4, ML / 64), 128>>>(x,   nullptr, Wq, Q, ML, 256, 256);
    gemm64<false, false><<<dim3(4, ML / 64), 128>>>(src, nullptr, Wk, K, ML, 256, 256);
    gemm64<false, false><<<dim3(4, ML / 64), 128>>>(src, nullptr, Wv, V, ML, 256, 256);

    // attention
    attn3<<<dim3(L_ / LT, SPLITS, B_), 256, ATTN_SMEM>>>(Q, K, V, af, OP, SS);
    combine_kernel<<<(B_ * L_ * D_ / 4) / 256, 256>>>(OP, SS, O);

    // output proj + LN1
    gemm64<false, false><<<dim3(4, ML / 64), 128>>>(O, nullptr, Wm, M, ML, 256, 256);
    ln_kernel<false><<<ML, 256>>>(M, g1, b1, nullptr, M);

    // MLP
    gemm64<true, true><<<dim3(8, ML / 64), 128>>>(x, M, W1, HB, ML, 512, 512);
    gemm64<false, false><<<dim3(4, ML / 64), 128>>>(HB, nullptr, W2, T, ML, 256, 512);

    // LN2 + residual -> out
    ln_kernel<true><<<ML, 256>>>(T, g2, b2, x, out);
}

// round 7
// speedup vs baseline: 1.0018x; 1.0018x over previous
#include <cuda_runtime.h>
#include <math.h>

typedef unsigned long long ull;
typedef unsigned int u32;

#define B_  2
#define L_  2048
#define S_  2048
#define D_  256
#define H_  8
#define SPLITS 2
#define SHALF (S_ / SPLITS)      // 1024
#define LT 16                    // l-rows per block
#define ST 16
#define NT (SHALF / ST)          // 64

// ---------------- f32x2 packed math ----------------
#define PACK2(d, x, y) asm("mov.b64 %0, {%1, %2};" : "=l"(d) : "r"(__float_as_uint(x)), "r"(__float_as_uint(y)))
#define UNPACK2(x, y, d) do { u32 _lo, _hi; \
    asm("mov.b64 {%0, %1}, %2;" : "=r"(_lo), "=r"(_hi) : "l"(d)); \
    (x) = __uint_as_float(_lo); (y) = __uint_as_float(_hi); } while (0)
#define FMA2(d, a, b, c) asm("fma.rn.f32x2 %0, %1, %2, %3;" : "=l"(d) : "l"(a), "l"(b), "l"(c))
#define MUL2(d, a, b)    asm("mul.rn.f32x2 %0, %1, %2;"     : "=l"(d) : "l"(a), "l"(b))
#define ADD2(d, a, b)    asm("add.rn.f32x2 %0, %1, %2;"     : "=l"(d) : "l"(a), "l"(b))

__device__ __forceinline__ float ex2f(float x) {
    float r;
    asm("ex2.approx.ftz.f32 %0, %1;" : "=f"(r) : "f"(x));
    return r;
}

// ---------------- scratch ----------------
__device__ float g_Q[(size_t)B_ * L_ * D_];
__device__ float g_K[(size_t)B_ * S_ * D_];
__device__ float g_V[(size_t)B_ * S_ * D_];
__device__ float g_OP[(size_t)SPLITS * B_ * L_ * D_];
__device__ float g_SS[(size_t)SPLITS * B_ * H_ * L_];
__device__ float g_O[(size_t)B_ * L_ * D_];
__device__ float g_M[(size_t)B_ * L_ * D_];
__device__ float g_HB[(size_t)B_ * L_ * 2 * D_];
__device__ float g_T[(size_t)B_ * L_ * D_];

// ---------------- GEMM: Y[M,N] = X[M,K] @ W[N,K]^T ----------------
// Tile 64x64, 128 threads, microtile 4(m)x8(n), f32x2 pairs along n.
// A stored DUPLICATED in smem so a-operands load as packed ull pairs (no PACK
// in the inner loop).
template <bool RELU, bool SPLIT>
__global__ void __launch_bounds__(128) gemm64(
    const float* __restrict__ X, const float* __restrict__ X2,
    const float* __restrict__ W, float* __restrict__ Y,
    int M, int N, int K) {
    __shared__ float XsD[16][140];  // [k][2*m duplicated], 16B-aligned rows
    __shared__ float BsT[16][72];   // [k][n]
    const int bm = blockIdx.y * 64, bn = blockIdx.x * 64;
    const int t = threadIdx.x, tx = t & 7, ty = t >> 3;
    const int NTk = K >> 4;

    float4 xr[2], wr[2];
    #pragma unroll
    for (int i = 0; i < 2; i++) {   // prologue load k-tile 0
        int idx = t + 128 * i; int r = idx >> 2; int c = (idx & 3) * 4;
        if (SPLIT) xr[i] = (c < 256) ? *(const float4*)(X + (size_t)(bm + r) * 256 + c)
                                     : *(const float4*)(X2 + (size_t)(bm + r) * 256 + (c - 256));
        else       xr[i] = *(const float4*)(X + (size_t)(bm + r) * K + c);
        wr[i] = *(const float4*)(W + (size_t)(bn + r) * K + c);
    }

    ull acc[4][4]; ull zero; PACK2(zero, 0.0f, 0.0f);
    #pragma unroll
    for (int m = 0; m < 4; m++)
        #pragma unroll
        for (int n = 0; n < 4; n++) acc[m][n] = zero;

    for (int kt = 0; kt < NTk; kt++) {
        __syncthreads();
        #pragma unroll
        for (int i = 0; i < 2; i++) {
            int idx = t + 128 * i; int r = idx >> 2; int c = (idx & 3) * 4;
            ull d;
            PACK2(d, xr[i].x, xr[i].x); *(ull*)&XsD[c + 0][2 * r] = d;
            PACK2(d, xr[i].y, xr[i].y); *(ull*)&XsD[c + 1][2 * r] = d;
            PACK2(d, xr[i].z, xr[i].z); *(ull*)&XsD[c + 2][2 * r] = d;
            PACK2(d, xr[i].w, xr[i].w); *(ull*)&XsD[c + 3][2 * r] = d;
            BsT[c + 0][r] = wr[i].x; BsT[c + 1][r] = wr[i].y;
            BsT[c + 2][r] = wr[i].z; BsT[c + 3][r] = wr[i].w;
        }
        if (kt + 1 < NTk) {
            int k0 = (kt + 1) * 16;
            #pragma unroll
            for (int i = 0; i < 2; i++) {
                int idx = t + 128 * i; int r = idx >> 2; int c = (idx & 3) * 4;
                int kc = k0 + c;
                if (SPLIT) xr[i] = (kc < 256) ? *(const float4*)(X + (size_t)(bm + r) * 256 + kc)
                                              : *(const float4*)(X2 + (size_t)(bm + r) * 256 + (kc - 256));
                else       xr[i] = *(const float4*)(X + (size_t)(bm + r) * K + kc);
                wr[i] = *(const float4*)(W + (size_t)(bn + r) * K + kc);
            }
        }
        __syncthreads();
        #pragma unroll
        for (int kk = 0; kk < 16; kk++) {
            ulonglong2 a01 = *(const ulonglong2*)&XsD[kk][ty * 8];      // (a0,a0),(a1,a1)
            ulonglong2 a23 = *(const ulonglong2*)&XsD[kk][ty * 8 + 4];  // (a2,a2),(a3,a3)
            ulonglong2 b01 = *(const ulonglong2*)&BsT[kk][tx * 8];
            ulonglong2 b23 = *(const ulonglong2*)&BsT[kk][tx * 8 + 4];
            FMA2(acc[0][0], a01.x, b01.x, acc[0][0]); FMA2(acc[0][1], a01.x, b01.y, acc[0][1]);
            FMA2(acc[0][2], a01.x, b23.x, acc[0][2]); FMA2(acc[0][3], a01.x, b23.y, acc[0][3]);
            FMA2(acc[1][0], a01.y, b01.x, acc[1][0]); FMA2(acc[1][1], a01.y, b01.y, acc[1][1]);
            FMA2(acc[1][2], a01.y, b23.x, acc[1][2]); FMA2(acc[1][3], a01.y, b23.y, acc[1][3]);
            FMA2(acc[2][0], a23.x, b01.x, acc[2][0]); FMA2(acc[2][1], a23.x, b01.y, acc[2][1]);
            FMA2(acc[2][2], a23.x, b23.x, acc[2][2]); FMA2(acc[2][3], a23.x, b23.y, acc[2][3]);
            FMA2(acc[3][0], a23.y, b01.x, acc[3][0]); FMA2(acc[3][1], a23.y, b01.y, acc[3][1]);
            FMA2(acc[3][2], a23.y, b23.x, acc[3][2]); FMA2(acc[3][3], a23.y, b23.y, acc[3][3]);
        }
    }

    float o[4][8];
    #pragma unroll
    for (int m = 0; m < 4; m++)
        #pragma unroll
        for (int np = 0; np < 4; np++)
            UNPACK2(o[m][2 * np], o[m][2 * np + 1], acc[m][np]);
    #pragma unroll
    for (int r = 0; r < 4; r++) {
        if (RELU)
            #pragma unroll
            for (int n = 0; n < 8; n++) o[r][n] = fmaxf(o[r][n], 0.0f);
        float4 w0, w1;
        w0.x = o[r][0]; w0.y = o[r][1]; w0.z = o[r][2]; w0.w = o[r][3];
        w1.x = o[r][4]; w1.y = o[r][5]; w1.z = o[r][6]; w1.w = o[r][7];
        float* yp = Y + (size_t)(bm + ty * 4 + r) * N + bn + tx * 8;
        *(float4*)yp = w0;
        *(float4*)(yp + 4) = w1;
    }
}

// ---------------- fused attention, dim-split (2 threads per row) ----------------
// Block: 256 threads = 8 warps (warp = head). lane&15 = l-row (16 rows/block),
// lane>>4 = dim-half (16 dims each). Score halves combined via shfl_xor(16).
// Grid: (L/16, SPLITS, B) = 512 blocks, 3 blocks/SM.
// smem: Ks[2][16][256] | Vs[2][16][256] | Afs[2][16][17] = 67712 bytes.
#define ATTN_SMEM 67712

#define ISSUE_KV(t_, buf_) do { \
    const float* ksrc_ = Kb + (size_t)(sbase + (t_) * ST) * D_; \
    const float* vsrc_ = Vb + (size_t)(sbase + (t_) * ST) * D_; \
    u32 kd_ = kbase + (u32)(buf_) * 16384; \
    u32 vd_ = vbase + (u32)(buf_) * 16384; \
    _Pragma("unroll") \
    for (int i_ = 0; i_ < 4; i_++) { \
        int idx_ = tid + 256 * i_; int s_ = idx_ >> 6; int c_ = (idx_ & 63) * 4; \
        asm volatile("cp.async.cg.shared.global [%0], [%1], 16;" :: \
            "r"(kd_ + (u32)(s_ * 256 + c_) * 4), "l"(ksrc_ + s_ * 256 + c_)); \
        asm volatile("cp.async.cg.shared.global [%0], [%1], 16;" :: \
            "r"(vd_ + (u32)(s_ * 256 + c_) * 4), "l"(vsrc_ + s_ * 256 + c_)); \
    } \
    asm volatile("cp.async.commit_group;"); \
} while (0)

#define LOAD_AF(t_) do { \
    afr = afb[(size_t)(tid >> 4) * S_ + (t_) * ST + (tid & 15)]; \
} while (0)

#define STORE_AF(buf_) do { \
    Afs[(buf_) * 272 + (tid >> 4) * 17 + (tid & 15)] = afr; \
} while (0)

__global__ void __launch_bounds__(256, 3) attn3(
    const float* __restrict__ Qg, const float* __restrict__ Kg,
    const float* __restrict__ Vg, const float* __restrict__ af,
    float* __restrict__ Op, float* __restrict__ SSp) {
    extern __shared__ float sm[];
    float* Ksm = sm;                 // 2*16*256 = 8192 floats
    float* Vsm = sm + 8192;          // 8192
    float* Afs = sm + 16384;         // 2*16*17 = 544

    const int b = blockIdx.z, sp = blockIdx.y;
    const int l0 = blockIdx.x * LT;
    const int tid = threadIdx.x;
    const int w = tid >> 5, lane = tid & 31;
    const int lr = lane & 15, half = lane >> 4;
    const int dimoff = w * 32 + half * 16;
    const int sbase = sp * SHALF;
    const float* Kb  = Kg + (size_t)b * S_ * D_;
    const float* Vb  = Vg + (size_t)b * S_ * D_;
    const float* afb = af + ((size_t)b * L_ + l0) * S_ + sbase;
    const u32 smb = (u32)__cvta_generic_to_shared(sm);
    const u32 kbase = smb;
    const u32 vbase = smb + 8192 * 4;

    // q regs: this thread's 16 dims, pre-scaled by log2(e)/sqrt(32)
    ull q[8];
    {
        const float QS = 0.25503486f;  // 1.4426950408889634 / sqrt(32)
        const float* qr = Qg + ((size_t)b * L_ + l0 + lr) * D_ + dimoff;
        #pragma unroll
        for (int i = 0; i < 4; i++) {
            float4 f = *(const float4*)(qr + i * 4);
            f.x *= QS; f.y *= QS; f.z *= QS; f.w *= QS;
            PACK2(q[2 * i], f.x, f.y);
            PACK2(q[2 * i + 1], f.z, f.w);
        }
    }
    ull zero; PACK2(zero, 0.0f, 0.0f);
    ull o[8];
    #pragma unroll
    for (int i = 0; i < 8; i++) o[i] = zero;
    float ssum = 0.0f;
    float afr;

    // prologue
    ISSUE_KV(0, 0);
    LOAD_AF(0);
    ISSUE_KV(1, 1);
    STORE_AF(0);
    LOAD_AF(1);

    for (int t = 0; t < NT; t++) {
        const int buf = t & 1;
        if (t + 1 < NT) asm volatile("cp.async.wait_group 1;");
        else            asm volatile("cp.async.wait_group 0;");
        __syncthreads();
        if (t + 1 < NT) STORE_AF(buf ^ 1);
        if (t + 2 < NT) LOAD_AF(t + 2);

        const float* ks  = Ksm + buf * 4096 + dimoff;
        const float* vs  = Vsm + buf * 4096 + dimoff;
        const float* afl = Afs + buf * 272 + lr * 17;

        #pragma unroll 4
        for (int s = 0; s < ST; s++) {
            const ulonglong2* kp = (const ulonglong2*)(ks + s * 256);
            ull a0, a1;
            {
                ulonglong2 kv = kp[0];
                MUL2(a0, q[0], kv.x); MUL2(a1, q[1], kv.y);
            }
            { ulonglong2 kv = kp[1]; FMA2(a0, q[2], kv.x, a0); FMA2(a1, q[3], kv.y, a1); }
            { ulonglong2 kv = kp[2]; FMA2(a0, q[4], kv.x, a0); FMA2(a1, q[5], kv.y, a1); }
            { ulonglong2 kv = kp[3]; FMA2(a0, q[6], kv.x, a0); FMA2(a1, q[7], kv.y, a1); }
            ADD2(a0, a0, a1);
            float x0, x1; UNPACK2(x0, x1, a0);
            float x = x0 + x1;
            x += __shfl_xor_sync(0xffffffffu, x, 16);   // combine dim halves
            float p = ex2f(x * afl[s]);
            ssum += p;
            ull pp; PACK2(pp, p, p);
            const ulonglong2* vp = (const ulonglong2*)(vs + s * 256);
            #pragma unroll
            for (int j = 0; j < 4; j++) {
                ulonglong2 vv = vp[j];
                FMA2(o[2 * j],     pp, vv.x, o[2 * j]);
                FMA2(o[2 * j + 1], pp, vv.y, o[2 * j + 1]);
            }
        }
        __syncthreads();
        if (t + 2 < NT) ISSUE_KV(t + 2, buf);
    }

    // write raw partials (division happens in combine)
    float* op = Op + (((size_t)sp * B_ + b) * L_ + l0 + lr) * D_ + dimoff;
    #pragma unroll
    for (int j = 0; j < 4; j++) {
        float v0, v1, v2, v3;
        UNPACK2(v0, v1, o[2 * j]);
        UNPACK2(v2, v3, o[2 * j + 1]);
        float4 f; f.x = v0; f.y = v1; f.z = v2; f.w = v3;
        *(float4*)(op + j * 4) = f;
    }
    if (half == 0)
        SSp[(((size_t)sp * B_ + b) * H_ + w) * L_ + l0 + lr] = ssum;
}

// ---------------- combine split partials: O = (O0+O1)/(s0+s1) ----------------
__global__ void combine_kernel(const float* __restrict__ Op, const float* __restrict__ SSp,
                               float* __restrict__ O) {
    size_t i = (size_t)blockIdx.x * 256 + threadIdx.x;   // per float4
    size_t e = i * 4;
    int d = (int)(e & 255);
    size_t bl = e >> 8;                 // b*L + l
    int h = d >> 5;
    size_t b = bl >> 11, l = bl & 2047;
    float4 a = *(const float4*)(Op + e);
    float4 c = *(const float4*)(Op + (size_t)B_ * L_ * D_ + e);
    float s = SSp[(b * H_ + h) * L_ + l] + SSp[((size_t)B_ * H_ + b * H_ + h) * L_ + l];
    float inv = 1.0f / s;
    float4 r;
    r.x = (a.x + c.x) * inv; r.y = (a.y + c.y) * inv;
    r.z = (a.z + c.z) * inv; r.w = (a.w + c.w) * inv;
    *(float4*)(O + e) = r;
}

// ---------------- LayerNorm over D=256 ----------------
template <bool RESID>
__global__ void ln_kernel(const float* __restrict__ in, const float* __restrict__ g,
                          const float* __restrict__ bt, const float* __restrict__ resid,
                          float* __restrict__ out) {
    const size_t row = blockIdx.x;
    const int tid = threadIdx.x;
    float x = in[row * D_ + tid];
    __shared__ float red[256];
    red[tid] = x; __syncthreads();
    #pragma unroll
    for (int off = 128; off > 0; off >>= 1) {
        if (tid < off) red[tid] += red[tid + off];
        __syncthreads();
    }
    const float mean = red[0] * (1.0f / D_);
    __syncthreads();
    const float d = x - mean;
    red[tid] = d * d; __syncthreads();
    #pragma unroll
    for (int off = 128; off > 0; off >>= 1) {
        if (tid < off) red[tid] += red[tid + off];
        __syncthreads();
    }
    const float var = red[0] * (1.0f / D_);
    float y = d * rsqrtf(var + 1e-5f) * g[tid] + bt[tid];
    if (RESID) y += resid[row * D_ + tid];
    out[row * D_ + tid] = y;
}

// ---------------- launch ----------------
extern "C" void kernel_launch(void* const* d_in, const int* in_sizes, int n_in,
                              void* d_out, int out_size) {
    const float* x   = (const float*)d_in[0];
    const float* src = (const float*)d_in[1];
    const float* af  = (const float*)d_in[2];
    const float* Wq  = (const float*)d_in[3];
    const float* Wk  = (const float*)d_in[4];
    const float* Wv  = (const float*)d_in[5];
    const float* Wm  = (const float*)d_in[6];
    const float* W1  = (const float*)d_in[7];
    const float* W2  = (const float*)d_in[8];
    const float* g1  = (const float*)d_in[9];
    const float* b1  = (const float*)d_in[10];
    const float* g2  = (const float*)d_in[11];
    const float* b2  = (const float*)d_in[12];
    float* out = (float*)d_out;

    float *Q, *K, *V, *OP, *SS, *O, *M, *HB, *T;
    cudaGetSymbolAddress((void**)&Q,  g_Q);
    cudaGetSymbolAddress((void**)&K,  g_K);
    cudaGetSymbolAddress((void**)&V,  g_V);
    cudaGetSymbolAddress((void**)&OP, g_OP);
    cudaGetSymbolAddress((void**)&SS, g_SS);
    cudaGetSymbolAddress((void**)&O,  g_O);
    cudaGetSymbolAddress((void**)&M,  g_M);
    cudaGetSymbolAddress((void**)&HB, g_HB);
    cudaGetSymbolAddress((void**)&T,  g_T);

    cudaFuncSetAttribute(attn3, cudaFuncAttributeMaxDynamicSharedMemorySize, ATTN_SMEM);

    const int ML = B_ * L_;  // 4096

    // projections
    gemm64<false, false><<<dim3(4, ML / 64), 128>>>(x,   nullptr, Wq, Q, ML, 256, 256);
    gemm64<false, false><<<dim3(4, ML / 64), 128>>>(src, nullptr, Wk, K, ML, 256, 256);
    gemm64<false, false><<<dim3(4, ML / 64), 128>>>(src, nullptr, Wv, V, ML, 256, 256);

    // attention
    attn3<<<dim3(L_ / LT, SPLITS, B_), 256, ATTN_SMEM>>>(Q, K, V, af, OP, SS);
    combine_kernel<<<(B_ * L_ * D_ / 4) / 256, 256>>>(OP, SS, O);

    // output proj + LN1
    gemm64<false, false><<<dim3(4, ML / 64), 128>>>(O, nullptr, Wm, M, ML, 256, 256);
    ln_kernel<false><<<ML, 256>>>(M, g1, b1, nullptr, M);

    // MLP
    gemm64<true, true><<<dim3(8, ML / 64), 128>>>(x, M, W1, HB, ML, 512, 512);
    gemm64<false, false><<<dim3(4, ML / 64), 128>>>(HB, nullptr, W2, T, ML, 256, 512);

    // LN2 + residual -> out
    ln_kernel<true><<<ML, 256>>>(T, g2, b2, x, out);
}

// round 8
// speedup vs baseline: 1.2029x; 1.2007x over previous
#include <cuda_runtime.h>
#include <math.h>

typedef unsigned long long ull;
typedef unsigned int u32;

#define B_  2
#define L_  2048
#define S_  2048
#define D_  256
#define H_  8
#define SPLITS 2
#define SHALF (S_ / SPLITS)      // 1024
#define LT 32                    // l-rows per block
#define ST 16
#define NT (SHALF / ST)          // 64

// ---------------- f32x2 packed math ----------------
#define PACK2(d, x, y) asm("mov.b64 %0, {%1, %2};" : "=l"(d) : "r"(__float_as_uint(x)), "r"(__float_as_uint(y)))
#define UNPACK2(x, y, d) do { u32 _lo, _hi; \
    asm("mov.b64 {%0, %1}, %2;" : "=r"(_lo), "=r"(_hi) : "l"(d)); \
    (x) = __uint_as_float(_lo); (y) = __uint_as_float(_hi); } while (0)
#define FMA2(d, a, b, c) asm("fma.rn.f32x2 %0, %1, %2, %3;" : "=l"(d) : "l"(a), "l"(b), "l"(c))
#define MUL2(d, a, b)    asm("mul.rn.f32x2 %0, %1, %2;"     : "=l"(d) : "l"(a), "l"(b))
#define ADD2(d, a, b)    asm("add.rn.f32x2 %0, %1, %2;"     : "=l"(d) : "l"(a), "l"(b))

__device__ __forceinline__ float ex2f(float x) {
    float r;
    asm("ex2.approx.ftz.f32 %0, %1;" : "=f"(r) : "f"(x));
    return r;
}

// ---------------- scratch ----------------
__device__ float g_Q[(size_t)B_ * L_ * D_];
__device__ float g_K[(size_t)B_ * S_ * D_];
__device__ float g_V[(size_t)B_ * S_ * D_];
__device__ float g_OP[(size_t)SPLITS * B_ * L_ * D_];
__device__ float g_SS[(size_t)SPLITS * B_ * H_ * L_];
__device__ float g_O[(size_t)B_ * L_ * D_];
__device__ float g_M[(size_t)B_ * L_ * D_];
__device__ float g_HB[(size_t)B_ * L_ * 2 * D_];
__device__ float g_T[(size_t)B_ * L_ * D_];

// ---------------- GEMM core (shared inner) ----------------
// Tile 64x64, 128 threads, microtile 4(m)x8(n), f32x2 pairs along n.
template <bool RELU, bool SPLIT>
__device__ __forceinline__ void gemm_body(
    const float* __restrict__ X, const float* __restrict__ X2,
    const float* __restrict__ W, float* __restrict__ Y,
    int N, int K, int bm, int bn) {
    __shared__ float XsT[16][68];   // [k][m]
    __shared__ float BsT[16][72];   // [k][n]
    const int t = threadIdx.x, tx = t & 7, ty = t >> 3;
    const int NTk = K >> 4;

    float4 xr[2], wr[2];
    #pragma unroll
    for (int i = 0; i < 2; i++) {   // prologue load k-tile 0
        int idx = t + 128 * i; int r = idx >> 2; int c = (idx & 3) * 4;
        if (SPLIT) xr[i] = (c < 256) ? *(const float4*)(X + (size_t)(bm + r) * 256 + c)
                                     : *(const float4*)(X2 + (size_t)(bm + r) * 256 + (c - 256));
        else       xr[i] = *(const float4*)(X + (size_t)(bm + r) * K + c);
        wr[i] = *(const float4*)(W + (size_t)(bn + r) * K + c);
    }

    ull acc[4][4]; ull zero; PACK2(zero, 0.0f, 0.0f);
    #pragma unroll
    for (int m = 0; m < 4; m++)
        #pragma unroll
        for (int n = 0; n < 4; n++) acc[m][n] = zero;

    for (int kt = 0; kt < NTk; kt++) {
        __syncthreads();
        #pragma unroll
        for (int i = 0; i < 2; i++) {
            int idx = t + 128 * i; int r = idx >> 2; int c = (idx & 3) * 4;
            XsT[c + 0][r] = xr[i].x; XsT[c + 1][r] = xr[i].y;
            XsT[c + 2][r] = xr[i].z; XsT[c + 3][r] = xr[i].w;
            BsT[c + 0][r] = wr[i].x; BsT[c + 1][r] = wr[i].y;
            BsT[c + 2][r] = wr[i].z; BsT[c + 3][r] = wr[i].w;
        }
        if (kt + 1 < NTk) {
            int k0 = (kt + 1) * 16;
            #pragma unroll
            for (int i = 0; i < 2; i++) {
                int idx = t + 128 * i; int r = idx >> 2; int c = (idx & 3) * 4;
                int kc = k0 + c;
                if (SPLIT) xr[i] = (kc < 256) ? *(const float4*)(X + (size_t)(bm + r) * 256 + kc)
                                              : *(const float4*)(X2 + (size_t)(bm + r) * 256 + (kc - 256));
                else       xr[i] = *(const float4*)(X + (size_t)(bm + r) * K + kc);
                wr[i] = *(const float4*)(W + (size_t)(bn + r) * K + kc);
            }
        }
        __syncthreads();
        #pragma unroll
        for (int kk = 0; kk < 16; kk++) {
            float4 a4 = *(const float4*)&XsT[kk][ty * 4];
            ulonglong2 b01 = *(const ulonglong2*)&BsT[kk][tx * 8];
            ulonglong2 b23 = *(const ulonglong2*)&BsT[kk][tx * 8 + 4];
            ull am;
            PACK2(am, a4.x, a4.x);
            FMA2(acc[0][0], am, b01.x, acc[0][0]); FMA2(acc[0][1], am, b01.y, acc[0][1]);
            FMA2(acc[0][2], am, b23.x, acc[0][2]); FMA2(acc[0][3], am, b23.y, acc[0][3]);
            PACK2(am, a4.y, a4.y);
            FMA2(acc[1][0], am, b01.x, acc[1][0]); FMA2(acc[1][1], am, b01.y, acc[1][1]);
            FMA2(acc[1][2], am, b23.x, acc[1][2]); FMA2(acc[1][3], am, b23.y, acc[1][3]);
            PACK2(am, a4.z, a4.z);
            FMA2(acc[2][0], am, b01.x, acc[2][0]); FMA2(acc[2][1], am, b01.y, acc[2][1]);
            FMA2(acc[2][2], am, b23.x, acc[2][2]); FMA2(acc[2][3], am, b23.y, acc[2][3]);
            PACK2(am, a4.w, a4.w);
            FMA2(acc[3][0], am, b01.x, acc[3][0]); FMA2(acc[3][1], am, b01.y, acc[3][1]);
            FMA2(acc[3][2], am, b23.x, acc[3][2]); FMA2(acc[3][3], am, b23.y, acc[3][3]);
        }
    }

    float o[4][8];
    #pragma unroll
    for (int m = 0; m < 4; m++)
        #pragma unroll
        for (int np = 0; np < 4; np++)
            UNPACK2(o[m][2 * np], o[m][2 * np + 1], acc[m][np]);
    #pragma unroll
    for (int r = 0; r < 4; r++) {
        if (RELU)
            #pragma unroll
            for (int n = 0; n < 8; n++) o[r][n] = fmaxf(o[r][n], 0.0f);
        float4 w0, w1;
        w0.x = o[r][0]; w0.y = o[r][1]; w0.z = o[r][2]; w0.w = o[r][3];
        w1.x = o[r][4]; w1.y = o[r][5]; w1.z = o[r][6]; w1.w = o[r][7];
        float* yp = Y + (size_t)(bm + ty * 4 + r) * N + bn + tx * 8;
        *(float4*)yp = w0;
        *(float4*)(yp + 4) = w1;
    }
}

template <bool RELU, bool SPLIT>
__global__ void __launch_bounds__(128) gemm64(
    const float* __restrict__ X, const float* __restrict__ X2,
    const float* __restrict__ W, float* __restrict__ Y,
    int N, int K) {
    gemm_body<RELU, SPLIT>(X, X2, W, Y, N, K, blockIdx.y * 64, blockIdx.x * 64);
}

// fused QKV projections: blockIdx.z selects (x,Wq)->Q / (src,Wk)->K / (src,Wv)->V
__global__ void __launch_bounds__(128) gemm_qkv(
    const float* __restrict__ x, const float* __restrict__ src,
    const float* __restrict__ Wq, const float* __restrict__ Wk,
    const float* __restrict__ Wv,
    float* __restrict__ Q, float* __restrict__ K, float* __restrict__ V) {
    const int z = blockIdx.z;
    const float* X = (z == 0) ? x : src;
    const float* W = (z == 0) ? Wq : (z == 1) ? Wk : Wv;
    float* Y = (z == 0) ? Q : (z == 1) ? K : V;
    gemm_body<false, false>(X, nullptr, W, Y, 256, 256, blockIdx.y * 64, blockIdx.x * 64);
}

// ---------------- fused attention: 2 rows/thread, shared K/V loads ----------------
// Block: 256 threads = 8 warps (warp = head), covers 32 l-rows.
// lane&15 = row pair (rows lr, lr+16); lane>>4 = dim-half (16 dims).
// Every K/V smem load serves TWO rows. Score halves combined via shfl_xor(16).
// Grid: (L/32, SPLITS, B) = 256 blocks, 2 blocks/SM.
// smem: Ks[2][16][256] | Vs[2][16][256] | Afs[2][32][17] = 70016 bytes.
#define ATTN_SMEM 70016

#define ISSUE_KV(t_, buf_) do { \
    const float* ksrc_ = Kb + (size_t)(sbase + (t_) * ST) * D_; \
    const float* vsrc_ = Vb + (size_t)(sbase + (t_) * ST) * D_; \
    u32 kd_ = kbase + (u32)(buf_) * 16384; \
    u32 vd_ = vbase + (u32)(buf_) * 16384; \
    _Pragma("unroll") \
    for (int i_ = 0; i_ < 4; i_++) { \
        int idx_ = tid + 256 * i_; int s_ = idx_ >> 6; int c_ = (idx_ & 63) * 4; \
        asm volatile("cp.async.cg.shared.global [%0], [%1], 16;" :: \
            "r"(kd_ + (u32)(s_ * 256 + c_) * 4), "l"(ksrc_ + s_ * 256 + c_)); \
        asm volatile("cp.async.cg.shared.global [%0], [%1], 16;" :: \
            "r"(vd_ + (u32)(s_ * 256 + c_) * 4), "l"(vsrc_ + s_ * 256 + c_)); \
    } \
    asm volatile("cp.async.commit_group;"); \
} while (0)

#define LOAD_AF(t_) do { \
    afr0 = afb[(size_t)(tid >> 4) * S_ + (t_) * ST + (tid & 15)]; \
    afr1 = afb[(size_t)((tid >> 4) + 16) * S_ + (t_) * ST + (tid & 15)]; \
} while (0)

#define STORE_AF(buf_) do { \
    Afs[(buf_) * 544 + (tid >> 4) * 17 + (tid & 15)] = afr0; \
    Afs[(buf_) * 544 + ((tid >> 4) + 16) * 17 + (tid & 15)] = afr1; \
} while (0)

__global__ void __launch_bounds__(256, 2) attn4(
    const float* __restrict__ Qg, const float* __restrict__ Kg,
    const float* __restrict__ Vg, const float* __restrict__ af,
    float* __restrict__ Op, float* __restrict__ SSp) {
    extern __shared__ float sm[];
    float* Ksm = sm;                 // 2*16*256 = 8192 floats
    float* Vsm = sm + 8192;          // 8192
    float* Afs = sm + 16384;         // 2*32*17 = 1088

    const int b = blockIdx.z, sp = blockIdx.y;
    const int l0 = blockIdx.x * LT;
    const int tid = threadIdx.x;
    const int w = tid >> 5, lane = tid & 31;
    const int lr = lane & 15, half = lane >> 4;
    const int dimoff = w * 32 + half * 16;
    const int sbase = sp * SHALF;
    const float* Kb  = Kg + (size_t)b * S_ * D_;
    const float* Vb  = Vg + (size_t)b * S_ * D_;
    const float* afb = af + ((size_t)b * L_ + l0) * S_ + sbase;
    const u32 smb = (u32)__cvta_generic_to_shared(sm);
    const u32 kbase = smb;
    const u32 vbase = smb + 8192 * 4;

    // q regs for both rows (16 dims each), pre-scaled by log2(e)/sqrt(32)
    ull q0[8], q1[8];
    {
        const float QS = 0.25503486f;  // 1.4426950408889634 / sqrt(32)
        const float* qr0 = Qg + ((size_t)b * L_ + l0 + lr) * D_ + dimoff;
        const float* qr1 = qr0 + 16 * D_;
        #pragma unroll
        for (int i = 0; i < 4; i++) {
            float4 f = *(const float4*)(qr0 + i * 4);
            f.x *= QS; f.y *= QS; f.z *= QS; f.w *= QS;
            PACK2(q0[2 * i], f.x, f.y);
            PACK2(q0[2 * i + 1], f.z, f.w);
            float4 g = *(const float4*)(qr1 + i * 4);
            g.x *= QS; g.y *= QS; g.z *= QS; g.w *= QS;
            PACK2(q1[2 * i], g.x, g.y);
            PACK2(q1[2 * i + 1], g.z, g.w);
        }
    }
    ull zero; PACK2(zero, 0.0f, 0.0f);
    ull o0[8], o1[8];
    #pragma unroll
    for (int i = 0; i < 8; i++) { o0[i] = zero; o1[i] = zero; }
    float ssum0 = 0.0f, ssum1 = 0.0f;
    float afr0, afr1;

    // prologue
    ISSUE_KV(0, 0);
    LOAD_AF(0);
    ISSUE_KV(1, 1);
    STORE_AF(0);
    LOAD_AF(1);

    for (int t = 0; t < NT; t++) {
        const int buf = t & 1;
        if (t + 1 < NT) asm volatile("cp.async.wait_group 1;");
        else            asm volatile("cp.async.wait_group 0;");
        __syncthreads();
        if (t + 1 < NT) STORE_AF(buf ^ 1);
        if (t + 2 < NT) LOAD_AF(t + 2);

        const float* ks   = Ksm + buf * 4096 + dimoff;
        const float* vs   = Vsm + buf * 4096 + dimoff;
        const float* afl0 = Afs + buf * 544 + lr * 17;
        const float* afl1 = afl0 + 16 * 17;

        #pragma unroll 4
        for (int s = 0; s < ST; s++) {
            const ulonglong2* kp = (const ulonglong2*)(ks + s * 256);
            ull a0, a1, c0, c1;
            {
                ulonglong2 kv = kp[0];
                MUL2(a0, q0[0], kv.x); MUL2(a1, q0[1], kv.y);
                MUL2(c0, q1[0], kv.x); MUL2(c1, q1[1], kv.y);
            }
            { ulonglong2 kv = kp[1];
              FMA2(a0, q0[2], kv.x, a0); FMA2(a1, q0[3], kv.y, a1);
              FMA2(c0, q1[2], kv.x, c0); FMA2(c1, q1[3], kv.y, c1); }
            { ulonglong2 kv = kp[2];
              FMA2(a0, q0[4], kv.x, a0); FMA2(a1, q0[5], kv.y, a1);
              FMA2(c0, q1[4], kv.x, c0); FMA2(c1, q1[5], kv.y, c1); }
            { ulonglong2 kv = kp[3];
              FMA2(a0, q0[6], kv.x, a0); FMA2(a1, q0[7], kv.y, a1);
              FMA2(c0, q1[6], kv.x, c0); FMA2(c1, q1[7], kv.y, c1); }
            ADD2(a0, a0, a1); ADD2(c0, c0, c1);
            float xa0, xa1, xc0, xc1;
            UNPACK2(xa0, xa1, a0);
            UNPACK2(xc0, xc1, c0);
            float xa = xa0 + xa1;
            float xc = xc0 + xc1;
            xa += __shfl_xor_sync(0xffffffffu, xa, 16);  // combine dim halves
            xc += __shfl_xor_sync(0xffffffffu, xc, 16);
            float p0 = ex2f(xa * afl0[s]);
            float p1 = ex2f(xc * afl1[s]);
            ssum0 += p0; ssum1 += p1;
            ull pp0, pp1; PACK2(pp0, p0, p0); PACK2(pp1, p1, p1);
            const ulonglong2* vp = (const ulonglong2*)(vs + s * 256);
            #pragma unroll
            for (int j = 0; j < 4; j++) {
                ulonglong2 vv = vp[j];
                FMA2(o0[2 * j],     pp0, vv.x, o0[2 * j]);
                FMA2(o0[2 * j + 1], pp0, vv.y, o0[2 * j + 1]);
                FMA2(o1[2 * j],     pp1, vv.x, o1[2 * j]);
                FMA2(o1[2 * j + 1], pp1, vv.y, o1[2 * j + 1]);
            }
        }
        __syncthreads();
        if (t + 2 < NT) ISSUE_KV(t + 2, buf);
    }

    // write raw partials (division happens in combine)
    float* op0 = Op + (((size_t)sp * B_ + b) * L_ + l0 + lr) * D_ + dimoff;
    float* op1 = op0 + 16 * D_;
    #pragma unroll
    for (int j = 0; j < 2; j++) {
        float v0, v1, v2, v3;
        UNPACK2(v0, v1, o0[2 * j * 2]);     UNPACK2(v2, v3, o0[2 * j * 2 + 1]);
        float4 f; f.x = v0; f.y = v1; f.z = v2; f.w = v3;
        *(float4*)(op0 + j * 8) = f;
        UNPACK2(v0, v1, o0[2 * j * 2 + 2]); UNPACK2(v2, v3, o0[2 * j * 2 + 3]);
        float4 g; g.x = v0; g.y = v1; g.z = v2; g.w = v3;
        *(float4*)(op0 + j * 8 + 4) = g;
        UNPACK2(v0, v1, o1[2 * j * 2]);     UNPACK2(v2, v3, o1[2 * j * 2 + 1]);
        float4 h; h.x = v0; h.y = v1; h.z = v2; h.w = v3;
        *(float4*)(op1 + j * 8) = h;
        UNPACK2(v0, v1, o1[2 * j * 2 + 2]); UNPACK2(v2, v3, o1[2 * j * 2 + 3]);
        float4 e; e.x = v0; e.y = v1; e.z = v2; e.w = v3;
        *(float4*)(op1 + j * 8 + 4) = e;
    }
    if (half == 0) {
        size_t ssb = (((size_t)sp * B_ + b) * H_ + w) * L_ + l0;
        SSp[ssb + lr] = ssum0;
        SSp[ssb + 16 + lr] = ssum1;
    }
}

// ---------------- combine split partials: O = (O0+O1)/(s0+s1) ----------------
__global__ void combine_kernel(const float* __restrict__ Op, const float* __restrict__ SSp,
                               float* __restrict__ O) {
    size_t i = (size_t)blockIdx.x * 256 + threadIdx.x;   // per float4
    size_t e = i * 4;
    int d = (int)(e & 255);
    size_t bl = e >> 8;                 // b*L + l
    int h = d >> 5;
    size_t b = bl >> 11, l = bl & 2047;
    float4 a = *(const float4*)(Op + e);
    float4 c = *(const float4*)(Op + (size_t)B_ * L_ * D_ + e);
    float s = SSp[(b * H_ + h) * L_ + l] + SSp[((size_t)B_ * H_ + b * H_ + h) * L_ + l];
    float inv = 1.0f / s;
    float4 r;
    r.x = (a.x + c.x) * inv; r.y = (a.y + c.y) * inv;
    r.z = (a.z + c.z) * inv; r.w = (a.w + c.w) * inv;
    *(float4*)(O + e) = r;
}

// ---------------- LayerNorm over D=256 ----------------
template <bool RESID>
__global__ void ln_kernel(const float* __restrict__ in, const float* __restrict__ g,
                          const float* __restrict__ bt, const float* __restrict__ resid,
                          float* __restrict__ out) {
    const size_t row = blockIdx.x;
    const int tid = threadIdx.x;
    float x = in[row * D_ + tid];
    __shared__ float red[256];
    red[tid] = x; __syncthreads();
    #pragma unroll
    for (int off = 128; off > 0; off >>= 1) {
        if (tid < off) red[tid] += red[tid + off];
        __syncthreads();
    }
    const float mean = red[0] * (1.0f / D_);
    __syncthreads();
    const float d = x - mean;
    red[tid] = d * d; __syncthreads();
    #pragma unroll
    for (int off = 128; off > 0; off >>= 1) {
        if (tid < off) red[tid] += red[tid + off];
        __syncthreads();
    }
    const float var = red[0] * (1.0f / D_);
    float y = d * rsqrtf(var + 1e-5f) * g[tid] + bt[tid];
    if (RESID) y += resid[row * D_ + tid];
    out[row * D_ + tid] = y;
}

// ---------------- launch ----------------
extern "C" void kernel_launch(void* const* d_in, const int* in_sizes, int n_in,
                              void* d_out, int out_size) {
    const float* x   = (const float*)d_in[0];
    const float* src = (const float*)d_in[1];
    const float* af  = (const float*)d_in[2];
    const float* Wq  = (const float*)d_in[3];
    const float* Wk  = (const float*)d_in[4];
    const float* Wv  = (const float*)d_in[5];
    const float* Wm  = (const float*)d_in[6];
    const float* W1  = (const float*)d_in[7];
    const float* W2  = (const float*)d_in[8];
    const float* g1  = (const float*)d_in[9];
    const float* b1  = (const float*)d_in[10];
    const float* g2  = (const float*)d_in[11];
    const float* b2  = (const float*)d_in[12];
    float* out = (float*)d_out;

    float *Q, *K, *V, *OP, *SS, *O, *M, *HB, *T;
    cudaGetSymbolAddress((void**)&Q,  g_Q);
    cudaGetSymbolAddress((void**)&K,  g_K);
    cudaGetSymbolAddress((void**)&V,  g_V);
    cudaGetSymbolAddress((void**)&OP, g_OP);
    cudaGetSymbolAddress((void**)&SS, g_SS);
    cudaGetSymbolAddress((void**)&O,  g_O);
    cudaGetSymbolAddress((void**)&M,  g_M);
    cudaGetSymbolAddress((void**)&HB, g_HB);
    cudaGetSymbolAddress((void**)&T,  g_T);

    cudaFuncSetAttribute(attn4, cudaFuncAttributeMaxDynamicSharedMemorySize, ATTN_SMEM);

    const int ML = B_ * L_;  // 4096

    // projections (one launch, grid.z selects Q/K/V)
    gemm_qkv<<<dim3(4, ML / 64, 3), 128>>>(x, src, Wq, Wk, Wv, Q, K, V);

    // attention
    attn4<<<dim3(L_ / LT, SPLITS, B_), 256, ATTN_SMEM>>>(Q, K, V, af, OP, SS);
    combine_kernel<<<(B_ * L_ * D_ / 4) / 256, 256>>>(OP, SS, O);

    // output proj + LN1
    gemm64<false, false><<<dim3(4, ML / 64), 128>>>(O, nullptr, Wm, M, 256, 256);
    ln_kernel<false><<<ML, 256>>>(M, g1, b1, nullptr, M);

    // MLP
    gemm64<true, true><<<dim3(8, ML / 64), 128>>>(x, M, W1, HB, 512, 512);
    gemm64<false, false><<<dim3(4, ML / 64), 128>>>(HB, nullptr, W2, T, 256, 512);

    // LN2 + residual -> out
    ln_kernel<true><<<ML, 256>>>(T, g2, b2, x, out);
}